// round 9
// baseline (speedup 1.0000x reference)
#include <cuda_runtime.h>
#include <cuda_bf16.h>
#include <cstdint>

// Problem constants (match reference)
#define HH 480
#define WW 640
#define NPIX (HH * WW)

// Device-global scratch (no allocation allowed).
// Zero-initialized at module load; finalize_kernel re-zeroes consumed words,
// so the "clear" invariant holds at the start of every launch/graph replay.
__device__ __align__(16) unsigned long long g_scr[NPIX];

// ---------------------------------------------------------------------------
// Packed f32x2 helpers (Blackwell: fma.rn.f32x2 / mul.rn.f32x2 / add.rn.f32x2
// are NOT generated by ptxas from C++ — inline PTX only). One 64-bit register
// holds the same variable for two independent points (lo = point A, hi = B).
// ---------------------------------------------------------------------------
typedef unsigned long long f2;

__device__ __forceinline__ f2 pk(float lo, float hi) {
    f2 r; asm("mov.b64 %0,{%1,%2};" : "=l"(r) : "f"(lo), "f"(hi)); return r;
}
__device__ __forceinline__ void upk(float& lo, float& hi, f2 v) {
    asm("mov.b64 {%0,%1},%2;" : "=f"(lo), "=f"(hi) : "l"(v));
}
__device__ __forceinline__ f2 ffma2(f2 a, f2 b, f2 c) {
    f2 d; asm("fma.rn.f32x2 %0,%1,%2,%3;" : "=l"(d) : "l"(a), "l"(b), "l"(c));
    return d;
}
__device__ __forceinline__ f2 fmul2(f2 a, f2 b) {
    f2 d; asm("mul.rn.f32x2 %0,%1,%2;" : "=l"(d) : "l"(a), "l"(b)); return d;
}
__device__ __forceinline__ f2 fneg2(f2 a) {            // exact sign flip
    return a ^ 0x8000000080000000ull;
}

// ---------------------------------------------------------------------------
// One-sided (Hestenes) Jacobi rotation on column pair (P,Q), two points at a
// time in f32x2. Semantics bit-identical to the scalar version: per-half the
// rotation fires iff apq^2 > 1e-14*app*aqq, else (c,s)=(1,0) (exact identity).
// Scalar MUFU angle chain per half; all bulk math packed.
// ---------------------------------------------------------------------------
template <int P, int Q>
__device__ __forceinline__ void osj2(f2 a[4][4], f2 v2[4], f2 v3[4]) {
    f2 apq = fmul2(a[P][0], a[Q][0]);
    f2 app = fmul2(a[P][0], a[P][0]);
    f2 aqq = fmul2(a[Q][0], a[Q][0]);
#pragma unroll
    for (int r = 1; r < 4; r++) {
        apq = ffma2(a[P][r], a[Q][r], apq);
        app = ffma2(a[P][r], a[P][r], app);
        aqq = ffma2(a[Q][r], a[Q][r], aqq);
    }
    float apq0, apq1, app0, app1, aqq0, aqq1;
    upk(apq0, apq1, apq);
    upk(app0, app1, app);
    upk(aqq0, aqq1, aqq);
    bool f0 = apq0 * apq0 > 1e-14f * app0 * aqq0;
    bool f1 = apq1 * apq1 > 1e-14f * app1 * aqq1;
    if (f0 | f1) {
        float c0 = 1.0f, s0 = 0.0f, c1 = 1.0f, s1 = 0.0f;
        if (f0) {
            float u = aqq0 - app0, w = 2.0f * apq0;
            float r2 = fmaf(u, u, w * w);
            float h = r2 * rsqrtf(r2);              // sqrt(u^2+w^2)
            float t = __fdividef(w, fabsf(u) + h);  // |t| <= 1
            t = (u >= 0.0f) ? t : -t;
            c0 = rsqrtf(fmaf(t, t, 1.0f));
            s0 = t * c0;
        }
        if (f1) {
            float u = aqq1 - app1, w = 2.0f * apq1;
            float r2 = fmaf(u, u, w * w);
            float h = r2 * rsqrtf(r2);
            float t = __fdividef(w, fabsf(u) + h);
            t = (u >= 0.0f) ? t : -t;
            c1 = rsqrtf(fmaf(t, t, 1.0f));
            s1 = t * c1;
        }
        f2 c = pk(c0, c1), s = pk(s0, s1), ns = fneg2(s);
#pragma unroll
        for (int r = 0; r < 4; r++) {
            f2 ap = a[P][r], aq = a[Q][r];
            a[P][r] = ffma2(c, ap, fmul2(ns, aq));  // c*ap - s*aq
            a[Q][r] = ffma2(s, ap, fmul2(c, aq));   // s*ap + c*aq
        }
        {
            f2 vp = v2[P], vq = v2[Q];
            v2[P] = ffma2(c, vp, fmul2(ns, vq));
            v2[Q] = ffma2(s, vp, fmul2(c, vq));
            vp = v3[P]; vq = v3[Q];
            v3[P] = ffma2(c, vp, fmul2(ns, vq));
            v3[Q] = ffma2(s, vp, fmul2(c, vq));
        }
    }
}

// ---------------------------------------------------------------------------
// Kernel 1: triangulation, TWO points per thread via f32x2 + scatter.
// P matrices computed per-block into shared memory (no separate setup kernel).
// out layout: [0, NPIX) depth image (finalize), [NPIX, NPIX+N) kp3d
// ---------------------------------------------------------------------------
__global__ __launch_bounds__(256)
void tri_kernel(const float* __restrict__ K0g,
                const float* __restrict__ K1g,
                const float* __restrict__ Tg,
                const float* __restrict__ mconf,
                const float* __restrict__ kp0,
                const float* __restrict__ kp1,
                float* __restrict__ out, int N) {
    // sP[0..11] = P0 = [K0|0], sP[12..23] = P1 = K1 @ T[:3,:]
    __shared__ float sP[24];
    int tid = threadIdx.x;
    if (tid < 24) {
        int idx = tid;
        int half = idx >= 12;
        int r = (idx - half * 12) / 4;
        int j = idx & 3;
        float v;
        if (!half) {
            v = (j < 3) ? K0g[r * 3 + j] : 0.0f;
        } else {
            v = K1g[r * 3 + 0] * Tg[0 * 4 + j];
            v = fmaf(K1g[r * 3 + 1], Tg[1 * 4 + j], v);
            v = fmaf(K1g[r * 3 + 2], Tg[2 * 4 + j], v);
        }
        sP[idx] = v;
    }
    __syncthreads();

    int i = blockIdx.x * blockDim.x + tid;   // pair index
    int n0 = 2 * i, n1 = 2 * i + 1;
    if (n0 >= N) return;
    bool dual = (n1 < N);

    f2 p0x, p0y, p1x, p1y, cf2;
    if (dual) {
        float4 q0 = reinterpret_cast<const float4*>(kp0)[i];  // A=(x,y) B=(z,w)
        float4 q1 = reinterpret_cast<const float4*>(kp1)[i];
        float2 cf = reinterpret_cast<const float2*>(mconf)[i];
        p0x = pk(q0.x, q0.z); p0y = pk(q0.y, q0.w);
        p1x = pk(q1.x, q1.z); p1y = pk(q1.y, q1.w);
        cf2 = pk(cf.x, cf.y);
    } else {                                  // odd tail: duplicate the point
        float2 q0 = reinterpret_cast<const float2*>(kp0)[n0];
        float2 q1 = reinterpret_cast<const float2*>(kp1)[n0];
        float cf = mconf[n0];
        p0x = pk(q0.x, q0.x); p0y = pk(q0.y, q0.y);
        p1x = pk(q1.x, q1.x); p1y = pk(q1.y, q1.y);
        cf2 = pk(cf, cf);
    }

    // A columns: a[col][row]; rows 0,1 view0 (w=1), rows 2,3 view1 (w=conf)
    f2 a[4][4];
#pragma unroll
    for (int j = 0; j < 4; j++) {
        float P00 = sP[0 * 4 + j], P01 = sP[1 * 4 + j], P02 = sP[2 * 4 + j];
        float P10 = sP[12 + 0 * 4 + j], P11 = sP[12 + 1 * 4 + j],
              P12 = sP[12 + 2 * 4 + j];
        a[j][0] = ffma2(p0x, pk(P02, P02), pk(-P00, -P00));
        a[j][1] = ffma2(p0y, pk(P02, P02), pk(-P01, -P01));
        a[j][2] = fmul2(ffma2(p1x, pk(P12, P12), pk(-P10, -P10)), cf2);
        a[j][3] = fmul2(ffma2(p1y, pk(P12, P12), pk(-P11, -P11)), cf2);
    }

    // V rows 2,3 (V starts as identity): 1.0f|1.0f packed = 0x3F8000003F800000
    f2 v2[4] = {0ull, 0ull, 0x3F8000003F800000ull, 0ull};
    f2 v3[4] = {0ull, 0ull, 0ull, 0x3F8000003F800000ull};

    // Cyclic one-sided Jacobi, 3 sweeps + per-half skip guard
#pragma unroll
    for (int sweep = 0; sweep < 3; sweep++) {
        osj2<0, 1>(a, v2, v3);
        osj2<0, 2>(a, v2, v3);
        osj2<0, 3>(a, v2, v3);
        osj2<1, 2>(a, v2, v3);
        osj2<1, 3>(a, v2, v3);
        osj2<2, 3>(a, v2, v3);
    }

    // Final column norms (packed), then per-half scalar argmin + output
    float nn0[4], nn1[4], w20[4], w21[4], w30[4], w31[4];
#pragma unroll
    for (int j = 0; j < 4; j++) {
        f2 s = fmul2(a[j][0], a[j][0]);
        s = ffma2(a[j][1], a[j][1], s);
        s = ffma2(a[j][2], a[j][2], s);
        s = ffma2(a[j][3], a[j][3], s);
        upk(nn0[j], nn1[j], s);
        upk(w20[j], w21[j], v2[j]);
        upk(w30[j], w31[j], v3[j]);
    }

#pragma unroll
    for (int h = 0; h < 2; h++) {
        if (h == 1 && !dual) break;
        const float* nn = h ? nn1 : nn0;
        const float* w2 = h ? w21 : w20;
        const float* w3 = h ? w31 : w30;
        float bestn = 3.4e38f, bv2 = 0.0f, bv3 = 0.0f;
#pragma unroll
        for (int j = 0; j < 4; j++)
            if (nn[j] < bestn) { bestn = nn[j]; bv2 = w2[j]; bv3 = w3[j]; }

        // z = v[2]/v[3] (sign cancels). IEEE div; inf/nan collapse to 0 below.
        float z = bv2 / bv3;
        z = fminf(fmaxf(z, -1000.0f), 1000.0f);
        float kp = (z > 0.0f && z < 30.0f) ? z : 0.0f;

        int n = n0 + h;
        out[NPIX + n] = kp;

        // Last-index-wins deterministic scatter
        float px, pxo, py, pyo;
        upk(px, pxo, p0x);
        upk(py, pyo, p0y);
        int xi = (int)(h ? pxo : px);
        int yi = (int)(h ? pyo : py);
        unsigned long long pkd =
            ((unsigned long long)(unsigned)(n + 1) << 32) |
            (unsigned long long)__float_as_uint(kp);
        atomicMax(&g_scr[yi * WW + xi], pkd);
    }
}

// ---------------------------------------------------------------------------
// Kernel 2: unpack scratch into depth image AND reset scratch for next launch.
// 2 pixels/thread via 16B loads.
// ---------------------------------------------------------------------------
__global__ void finalize_kernel(float* __restrict__ out) {
    int i = blockIdx.x * blockDim.x + threadIdx.x;   // pair index
    if (i < NPIX / 2) {
        ulonglong2 p = reinterpret_cast<ulonglong2*>(g_scr)[i];
        float2 o;
        o.x = (p.x != 0ull) ? __uint_as_float((unsigned)p.x) : 0.0f;
        o.y = (p.y != 0ull) ? __uint_as_float((unsigned)p.y) : 0.0f;
        reinterpret_cast<float2*>(out)[i] = o;
        if (p.x != 0ull) g_scr[2 * i + 0] = 0ull;    // restore clear invariant
        if (p.y != 0ull) g_scr[2 * i + 1] = 0ull;
    }
}

// ---------------------------------------------------------------------------
// kernel_launch
// Inputs: T_0to1[16], K0[9], K1[9], mconf[N], mkpts0_f[2N], mkpts1_f[2N],
//         image0[307200], m_bids[N]
// Output: depth0_sparse [307200] ++ kp3d_val [N]
// ---------------------------------------------------------------------------
extern "C" void kernel_launch(void* const* d_in, const int* in_sizes, int n_in,
                              void* d_out, int out_size) {
    const float* T    = (const float*)d_in[0];
    const float* K0   = (const float*)d_in[1];
    const float* K1   = (const float*)d_in[2];
    const float* conf = (const float*)d_in[3];
    const float* kp0  = (const float*)d_in[4];
    const float* kp1  = (const float*)d_in[5];
    float* out = (float*)d_out;
    int N = in_sizes[3];

    int pairs = (N + 1) / 2;
    tri_kernel<<<(pairs + 255) / 256, 256>>>(K0, K1, T, conf, kp0, kp1, out, N);
    finalize_kernel<<<(NPIX / 2 + 255) / 256, 256>>>(out);
}

// round 10
// speedup vs baseline: 1.0786x; 1.0786x over previous
#include <cuda_runtime.h>
#include <cuda_bf16.h>
#include <cstdint>

// Problem constants (match reference)
#define HH 480
#define WW 640
#define NPIX (HH * WW)

// Device-global scratch (no allocation allowed).
// Zero-initialized at module load; finalize_kernel re-zeroes all words,
// so the "clear" invariant holds at the start of every launch/graph replay.
__device__ __align__(16) unsigned long long g_scr[NPIX];

// ---------------------------------------------------------------------------
// One-sided (Hestenes) Jacobi rotation on column pair (P,Q) of A, stored
// column-major a[col][row]. Pair quantities computed fresh from live columns
// (no incremental drift); converged pairs are skipped, never garbage-rotated.
// Scaled angle: h = sqrt(u^2 + w^2), t = sgn(u) * w / (|u| + h)  (1 division).
// v2/v3 = rows 2,3 of accumulated V (the only rows the output needs).
// ---------------------------------------------------------------------------
template <int P, int Q>
__device__ __forceinline__ void osj(float a[4][4], float v2[4], float v3[4]) {
    float apq = a[P][0] * a[Q][0];
    float app = a[P][0] * a[P][0];
    float aqq = a[Q][0] * a[Q][0];
#pragma unroll
    for (int r = 1; r < 4; r++) {
        apq = fmaf(a[P][r], a[Q][r], apq);
        app = fmaf(a[P][r], a[P][r], app);
        aqq = fmaf(a[Q][r], a[Q][r], aqq);
    }
    // Skip if already orthogonal at fp32 resolution (guards late sweeps).
    if (apq * apq > 1e-14f * app * aqq) {
        float u = aqq - app;
        float w = 2.0f * apq;
        float r2 = fmaf(u, u, w * w);          // > 0 since w != 0 here
        float h = r2 * rsqrtf(r2);             // sqrt(u^2 + w^2)
        float t = __fdividef(w, fabsf(u) + h); // |t| <= 1
        t = (u >= 0.0f) ? t : -t;
        float c = rsqrtf(fmaf(t, t, 1.0f));
        float s = t * c;

#pragma unroll
        for (int r = 0; r < 4; r++) {
            float ap = a[P][r], aq = a[Q][r];
            a[P][r] = c * ap - s * aq;
            a[Q][r] = s * ap + c * aq;
        }
        {
            float vp = v2[P], vq = v2[Q];
            v2[P] = c * vp - s * vq;
            v2[Q] = s * vp + c * vq;
            vp = v3[P]; vq = v3[Q];
            v3[P] = c * vp - s * vq;
            v3[Q] = s * vp + c * vq;
        }
    }
}

// ---------------------------------------------------------------------------
// Kernel 1: per-point triangulation (one-sided Jacobi SVD of 4x4 A) + scatter.
// P matrices computed per-block into shared memory (no separate setup kernel).
// out layout: [0, NPIX) depth image (finalize), [NPIX, NPIX+N) kp3d
// ---------------------------------------------------------------------------
__global__ __launch_bounds__(256)
void tri_kernel(const float* __restrict__ K0g,
                const float* __restrict__ K1g,
                const float* __restrict__ Tg,
                const float* __restrict__ mconf,
                const float* __restrict__ kp0,
                const float* __restrict__ kp1,
                float* __restrict__ out, int N) {
    // sP[0..11] = P0 = [K0|0], sP[12..23] = P1 = K1 @ T[:3,:]
    __shared__ float sP[24];
    int tid = threadIdx.x;
    if (tid < 24) {
        int idx = tid;
        int half = idx >= 12;
        int r = (idx - half * 12) / 4;
        int j = idx & 3;
        float v;
        if (!half) {
            v = (j < 3) ? K0g[r * 3 + j] : 0.0f;
        } else {
            v = K1g[r * 3 + 0] * Tg[0 * 4 + j];
            v = fmaf(K1g[r * 3 + 1], Tg[1 * 4 + j], v);
            v = fmaf(K1g[r * 3 + 2], Tg[2 * 4 + j], v);
        }
        sP[idx] = v;
    }
    __syncthreads();

    int n = blockIdx.x * blockDim.x + tid;
    if (n >= N) return;

    float2 p0 = reinterpret_cast<const float2*>(kp0)[n];
    float2 p1 = reinterpret_cast<const float2*>(kp1)[n];
    float conf = mconf[n];

    // A columns: a[col][row]; rows 0,1 from view0 (w=1), rows 2,3 view1 (w=conf)
    float a[4][4];
#pragma unroll
    for (int j = 0; j < 4; j++) {
        float P00 = sP[0 * 4 + j], P01 = sP[1 * 4 + j], P02 = sP[2 * 4 + j];
        float P10 = sP[12 + 0 * 4 + j], P11 = sP[12 + 1 * 4 + j],
              P12 = sP[12 + 2 * 4 + j];
        a[j][0] = fmaf(p0.x, P02, -P00);
        a[j][1] = fmaf(p0.y, P02, -P01);
        a[j][2] = fmaf(p1.x, P12, -P10) * conf;
        a[j][3] = fmaf(p1.y, P12, -P11) * conf;
    }

    // V rows 2 and 3 (V starts as identity)
    float v2[4] = {0.0f, 0.0f, 1.0f, 0.0f};
    float v3[4] = {0.0f, 0.0f, 0.0f, 1.0f};

    // Cyclic one-sided Jacobi, 3 sweeps + skip guard
#pragma unroll
    for (int sweep = 0; sweep < 3; sweep++) {
        osj<0, 1>(a, v2, v3);
        osj<0, 2>(a, v2, v3);
        osj<0, 3>(a, v2, v3);
        osj<1, 2>(a, v2, v3);
        osj<1, 3>(a, v2, v3);
        osj<2, 3>(a, v2, v3);
    }

    // Exact final column norms; argmin -> V column of smallest singular value
    float bestn = 3.4e38f, bv2 = 0.0f, bv3 = 0.0f;
#pragma unroll
    for (int j = 0; j < 4; j++) {
        float s = a[j][0] * a[j][0];
        s = fmaf(a[j][1], a[j][1], s);
        s = fmaf(a[j][2], a[j][2], s);
        s = fmaf(a[j][3], a[j][3], s);
        if (s < bestn) { bestn = s; bv2 = v2[j]; bv3 = v3[j]; }
    }

    // z = v[2]/v[3] (sign cancels). IEEE div; inf/nan collapse to 0 below.
    float z = bv2 / bv3;
    z = fminf(fmaxf(z, -1000.0f), 1000.0f);
    float kp = (z > 0.0f && z < 30.0f) ? z : 0.0f;

    out[NPIX + n] = kp;

    // Last-index-wins deterministic scatter
    int xi = (int)p0.x;
    int yi = (int)p0.y;
    unsigned long long pk =
        ((unsigned long long)(unsigned)(n + 1) << 32) |
        (unsigned long long)__float_as_uint(kp);
    atomicMax(&g_scr[yi * WW + xi], pk);
}

// ---------------------------------------------------------------------------
// Kernel 2 (PDL secondary): unpack scratch into depth image AND reset scratch.
// cudaGridDependencySynchronize() orders all tri_kernel memory ops before the
// g_scr reads; the launch/prologue overlaps tri's tail drain.
// 2 pixels/thread, 16B load + unconditional 16B zero-store.
// ---------------------------------------------------------------------------
__global__ void finalize_kernel(float* __restrict__ out) {
    int i = blockIdx.x * blockDim.x + threadIdx.x;   // pair index
    cudaGridDependencySynchronize();
    if (i < NPIX / 2) {
        ulonglong2 p = reinterpret_cast<ulonglong2*>(g_scr)[i];
        float2 o;
        o.x = (p.x != 0ull) ? __uint_as_float((unsigned)p.x) : 0.0f;
        o.y = (p.y != 0ull) ? __uint_as_float((unsigned)p.y) : 0.0f;
        reinterpret_cast<float2*>(out)[i] = o;
        ulonglong2 zz; zz.x = 0ull; zz.y = 0ull;     // restore clear invariant
        reinterpret_cast<ulonglong2*>(g_scr)[i] = zz;
    }
}

// ---------------------------------------------------------------------------
// kernel_launch
// Inputs: T_0to1[16], K0[9], K1[9], mconf[N], mkpts0_f[2N], mkpts1_f[2N],
//         image0[307200], m_bids[N]
// Output: depth0_sparse [307200] ++ kp3d_val [N]
// ---------------------------------------------------------------------------
extern "C" void kernel_launch(void* const* d_in, const int* in_sizes, int n_in,
                              void* d_out, int out_size) {
    const float* T    = (const float*)d_in[0];
    const float* K0   = (const float*)d_in[1];
    const float* K1   = (const float*)d_in[2];
    const float* conf = (const float*)d_in[3];
    const float* kp0  = (const float*)d_in[4];
    const float* kp1  = (const float*)d_in[5];
    float* out = (float*)d_out;
    int N = in_sizes[3];

    tri_kernel<<<(N + 255) / 256, 256>>>(K0, K1, T, conf, kp0, kp1, out, N);

    // finalize via PDL: overlap its launch with tri's tail.
    cudaLaunchConfig_t cfg = {};
    cfg.gridDim = dim3((NPIX / 2 + 255) / 256, 1, 1);
    cfg.blockDim = dim3(256, 1, 1);
    cfg.dynamicSmemBytes = 0;
    cfg.stream = 0;
    cudaLaunchAttribute attrs[1];
    attrs[0].id = cudaLaunchAttributeProgrammaticStreamSerialization;
    attrs[0].val.programmaticStreamSerializationAllowed = 1;
    cfg.attrs = attrs;
    cfg.numAttrs = 1;
    cudaLaunchKernelEx(&cfg, finalize_kernel, out);
}

// round 13
// speedup vs baseline: 1.1321x; 1.0496x over previous
#include <cuda_runtime.h>
#include <cuda_bf16.h>
#include <cstdint>

// Problem constants (match reference)
#define HH 480
#define WW 640
#define NPIX (HH * WW)

// Device-global scratch (no allocation allowed).
// Zero-initialized at module load; finalize_kernel re-zeroes all words,
// so the "clear" invariant holds at the start of every launch/graph replay.
__device__ __align__(16) unsigned long long g_scr[NPIX];

// ---------------------------------------------------------------------------
// Gram entries of column pair (P,Q), fresh from live columns (load-bearing
// for numerics — incremental norms reintroduce cond^2 mixing, see R1/R2).
// ---------------------------------------------------------------------------
template <int P, int Q>
__device__ __forceinline__ void gram(const float a[4][4], float& app,
                                     float& aqq, float& apq) {
    apq = a[P][0] * a[Q][0];
    app = a[P][0] * a[P][0];
    aqq = a[Q][0] * a[Q][0];
#pragma unroll
    for (int r = 1; r < 4; r++) {
        apq = fmaf(a[P][r], a[Q][r], apq);
        app = fmaf(a[P][r], a[P][r], app);
        aqq = fmaf(a[Q][r], a[Q][r], aqq);
    }
}

// Branchless rotation angle: converged pairs select exact identity (1,0)
// instead of branching (warp-level issue cost is paid anyway; this drops
// BSSY/BSYNC and protects against apq==0 NaN paths via the select).
__device__ __forceinline__ void angle_cs(float app, float aqq, float apq,
                                         float& c, float& s) {
    bool fire = apq * apq > 1e-14f * app * aqq;
    float u = aqq - app;
    float w = 2.0f * apq;
    float r2 = fmaf(u, u, w * w);
    float h = r2 * rsqrtf(r2);              // sqrt(u^2+w^2); NaN if r2==0
    float t = __fdividef(w, fabsf(u) + h);  // |t| <= 1
    t = (u >= 0.0f) ? t : -t;
    float cc = rsqrtf(fmaf(t, t, 1.0f));
    float ss = t * cc;
    c = fire ? cc : 1.0f;                   // select discards any NaN path
    s = fire ? ss : 0.0f;
}

// Apply rotation to A columns P,Q (c=1,s=0 is an exact identity under FMA).
template <int P, int Q>
__device__ __forceinline__ void rotA(float a[4][4], float c, float s) {
#pragma unroll
    for (int r = 0; r < 4; r++) {
        float ap = a[P][r], aq = a[Q][r];
        a[P][r] = c * ap - s * aq;
        a[Q][r] = s * ap + c * aq;
    }
}

// Generic rotation (dense V rows) — used for sweeps 2 and 3.
template <int P, int Q>
__device__ __forceinline__ void rot_full(float a[4][4], float v2[4],
                                         float v3[4]) {
    float app, aqq, apq;
    gram<P, Q>(a, app, aqq, apq);
    float c, s;
    angle_cs(app, aqq, apq, c, s);
    rotA<P, Q>(a, c, s);
    float vp = v2[P], vq = v2[Q];
    v2[P] = c * vp - s * vq;
    v2[Q] = s * vp + c * vq;
    vp = v3[P]; vq = v3[Q];
    v3[P] = c * vp - s * vq;
    v3[Q] = s * vp + c * vq;
}

// ---------------------------------------------------------------------------
// Kernel 1: per-point triangulation (one-sided Jacobi SVD of 4x4 A) + scatter.
// P matrices computed per-block into shared memory (no separate setup kernel).
// out layout: [0, NPIX) depth image (finalize), [NPIX, NPIX+N) kp3d
// ---------------------------------------------------------------------------
__global__ __launch_bounds__(256)
void tri_kernel(const float* __restrict__ K0g,
                const float* __restrict__ K1g,
                const float* __restrict__ Tg,
                const float* __restrict__ mconf,
                const float* __restrict__ kp0,
                const float* __restrict__ kp1,
                float* __restrict__ out, int N) {
    // sP[0..11] = P0 = [K0|0], sP[12..23] = P1 = K1 @ T[:3,:]
    __shared__ float sP[24];
    int tid = threadIdx.x;
    if (tid < 24) {
        int idx = tid;
        int half = idx >= 12;
        int r = (idx - half * 12) / 4;
        int j = idx & 3;
        float v;
        if (!half) {
            v = (j < 3) ? K0g[r * 3 + j] : 0.0f;
        } else {
            v = K1g[r * 3 + 0] * Tg[0 * 4 + j];
            v = fmaf(K1g[r * 3 + 1], Tg[1 * 4 + j], v);
            v = fmaf(K1g[r * 3 + 2], Tg[2 * 4 + j], v);
        }
        sP[idx] = v;
    }
    __syncthreads();

    int n = blockIdx.x * blockDim.x + tid;
    if (n >= N) return;

    float2 p0 = reinterpret_cast<const float2*>(kp0)[n];
    float2 p1 = reinterpret_cast<const float2*>(kp1)[n];
    float conf = mconf[n];

    // A columns: a[col][row]; rows 0,1 from view0 (w=1), rows 2,3 view1 (w=conf)
    float a[4][4];
#pragma unroll
    for (int j = 0; j < 4; j++) {
        float P00 = sP[0 * 4 + j], P01 = sP[1 * 4 + j], P02 = sP[2 * 4 + j];
        float P10 = sP[12 + 0 * 4 + j], P11 = sP[12 + 1 * 4 + j],
              P12 = sP[12 + 2 * 4 + j];
        a[j][0] = fmaf(p0.x, P02, -P00);
        a[j][1] = fmaf(p0.y, P02, -P01);
        a[j][2] = fmaf(p1.x, P12, -P10) * conf;
        a[j][3] = fmaf(p1.y, P12, -P11) * conf;
    }

    float v2[4], v3[4];

    // ---- Sweep 1: V starts as identity rows e2/e3; statically track zeros.
    {
        float app, aqq, apq, c, s;
        // (0,1): V rows untouched (slots 0,1 are zero in both)
        gram<0, 1>(a, app, aqq, apq);
        angle_cs(app, aqq, apq, c, s);
        rotA<0, 1>(a, c, s);
        // (0,2): v2 (0,·,1,·) -> (-s, ·, c, ·)
        gram<0, 2>(a, app, aqq, apq);
        angle_cs(app, aqq, apq, c, s);
        rotA<0, 2>(a, c, s);
        v2[0] = -s; v2[2] = c;
        // (0,3): v2 slots (x,0) -> (c x, s x); v3 (0,·,·,1) -> (-s, ·, ·, c)
        gram<0, 3>(a, app, aqq, apq);
        angle_cs(app, aqq, apq, c, s);
        rotA<0, 3>(a, c, s);
        { float x = v2[0]; v2[0] = c * x; v2[3] = s * x; }
        v3[0] = -s; v3[3] = c;
        // (1,2): v2 slots (0,y) -> (-s y, c y); v3 slots both zero
        gram<1, 2>(a, app, aqq, apq);
        angle_cs(app, aqq, apq, c, s);
        rotA<1, 2>(a, c, s);
        { float y = v2[2]; v2[1] = -s * y; v2[2] = c * y; }
        // (1,3): v2 dense pair; v3 slots (0,w) -> (-s w, c w)
        gram<1, 3>(a, app, aqq, apq);
        angle_cs(app, aqq, apq, c, s);
        rotA<1, 3>(a, c, s);
        { float vp = v2[1], vq = v2[3];
          v2[1] = c * vp - s * vq; v2[3] = s * vp + c * vq; }
        { float w = v3[3]; v3[1] = -s * w; v3[3] = c * w; }
        // (2,3): v2 dense pair; v3 slots (0,w) -> (-s w, c w)
        gram<2, 3>(a, app, aqq, apq);
        angle_cs(app, aqq, apq, c, s);
        rotA<2, 3>(a, c, s);
        { float vp = v2[2], vq = v2[3];
          v2[2] = c * vp - s * vq; v2[3] = s * vp + c * vq; }
        { float w = v3[3]; v3[2] = -s * w; v3[3] = c * w; }
    }

    // ---- Sweeps 2 and 3: generic dense rotations (branchless identity
    // fallback). Sweep 3 is load-bearing: 2 sweeps measured 1.69e-3 (FAIL),
    // 3 sweeps 9.84e-6 (PASS). Do not remove.
#pragma unroll
    for (int sweep = 0; sweep < 2; sweep++) {
        rot_full<0, 1>(a, v2, v3);
        rot_full<0, 2>(a, v2, v3);
        rot_full<0, 3>(a, v2, v3);
        rot_full<1, 2>(a, v2, v3);
        rot_full<1, 3>(a, v2, v3);
        rot_full<2, 3>(a, v2, v3);
    }

    // Final column norms; argmin -> V column of smallest singular value
    float bestn = 3.4e38f, bv2 = 0.0f, bv3 = 0.0f;
#pragma unroll
    for (int j = 0; j < 4; j++) {
        float s = a[j][0] * a[j][0];
        s = fmaf(a[j][1], a[j][1], s);
        s = fmaf(a[j][2], a[j][2], s);
        s = fmaf(a[j][3], a[j][3], s);
        if (s < bestn) { bestn = s; bv2 = v2[j]; bv3 = v3[j]; }
    }

    // z = v[2]/v[3] (sign cancels). IEEE div; inf/nan collapse to 0 below.
    float z = bv2 / bv3;
    z = fminf(fmaxf(z, -1000.0f), 1000.0f);
    float kp = (z > 0.0f && z < 30.0f) ? z : 0.0f;

    out[NPIX + n] = kp;

    // Last-index-wins deterministic scatter
    int xi = (int)p0.x;
    int yi = (int)p0.y;
    unsigned long long pk =
        ((unsigned long long)(unsigned)(n + 1) << 32) |
        (unsigned long long)__float_as_uint(kp);
    atomicMax(&g_scr[yi * WW + xi], pk);
}

// ---------------------------------------------------------------------------
// Kernel 2 (PDL secondary): unpack scratch into depth image AND reset scratch.
// ---------------------------------------------------------------------------
__global__ void finalize_kernel(float* __restrict__ out) {
    int i = blockIdx.x * blockDim.x + threadIdx.x;   // pair index
    cudaGridDependencySynchronize();
    if (i < NPIX / 2) {
        ulonglong2 p = reinterpret_cast<ulonglong2*>(g_scr)[i];
        float2 o;
        o.x = (p.x != 0ull) ? __uint_as_float((unsigned)p.x) : 0.0f;
        o.y = (p.y != 0ull) ? __uint_as_float((unsigned)p.y) : 0.0f;
        reinterpret_cast<float2*>(out)[i] = o;
        ulonglong2 zz; zz.x = 0ull; zz.y = 0ull;     // restore clear invariant
        reinterpret_cast<ulonglong2*>(g_scr)[i] = zz;
    }
}

// ---------------------------------------------------------------------------
// kernel_launch
// Inputs: T_0to1[16], K0[9], K1[9], mconf[N], mkpts0_f[2N], mkpts1_f[2N],
//         image0[307200], m_bids[N]
// Output: depth0_sparse [307200] ++ kp3d_val [N]
// ---------------------------------------------------------------------------
extern "C" void kernel_launch(void* const* d_in, const int* in_sizes, int n_in,
                              void* d_out, int out_size) {
    const float* T    = (const float*)d_in[0];
    const float* K0   = (const float*)d_in[1];
    const float* K1   = (const float*)d_in[2];
    const float* conf = (const float*)d_in[3];
    const float* kp0  = (const float*)d_in[4];
    const float* kp1  = (const float*)d_in[5];
    float* out = (float*)d_out;
    int N = in_sizes[3];

    tri_kernel<<<(N + 255) / 256, 256>>>(K0, K1, T, conf, kp0, kp1, out, N);

    // finalize via PDL: overlap its launch with tri's tail.
    cudaLaunchConfig_t cfg = {};
    cfg.gridDim = dim3((NPIX / 2 + 255) / 256, 1, 1);
    cfg.blockDim = dim3(256, 1, 1);
    cfg.dynamicSmemBytes = 0;
    cfg.stream = 0;
    cudaLaunchAttribute attrs[1];
    attrs[0].id = cudaLaunchAttributeProgrammaticStreamSerialization;
    attrs[0].val.programmaticStreamSerializationAllowed = 1;
    cfg.attrs = attrs;
    cfg.numAttrs = 1;
    cudaLaunchKernelEx(&cfg, finalize_kernel, out);
}